// round 13
// baseline (speedup 1.0000x reference)
#include <cuda_runtime.h>
#include <math.h>
#include <stdint.h>

#define NT 1024
#define NV 128
#define NXS 512
#define NVX 65536          // NV*NXS (contraction length of GEMM1)
#define KDIM 257
#define KP 288             // padded KDIM
#define NXOUT 2048
#define NH 48              // padded hidden+1 (33 -> 48)

// -------- scratch (no allocations allowed) --------
__device__ float g_h2T[(size_t)NH * NVX];      // [j][p]: relu layer-2 (j<32), ones (j=32), 0 pad
__device__ float g_w2[(size_t)NT * NH];        // f @ [H2|1]  (1024 x 48)
__device__ float g_w[(size_t)NT * KP];         // weights (1024 x 288)
__device__ float g_phiT[(size_t)NXOUT * KP];   // fourier basis transposed [n][k], tf32-rounded

// ============================ helpers ============================
__device__ __forceinline__ uint32_t smem_u32(const void* p) {
    uint32_t a;
    asm("{ .reg .u64 t; cvta.to.shared.u64 t, %1; cvt.u32.u64 %0, t; }" : "=r"(a) : "l"(p));
    return a;
}
__device__ __forceinline__ uint32_t rna_tf32(float x) {
    uint32_t r;
    asm("cvt.rna.tf32.f32 %0, %1;" : "=r"(r) : "f"(x));
    return r;
}
__device__ __forceinline__ void mma_tf32(float* c, const uint32_t* a, uint32_t b0, uint32_t b1) {
    asm volatile(
        "mma.sync.aligned.m16n8k8.row.col.f32.tf32.tf32.f32 "
        "{%0,%1,%2,%3}, {%4,%5,%6,%7}, {%8,%9}, {%0,%1,%2,%3};"
        : "+f"(c[0]), "+f"(c[1]), "+f"(c[2]), "+f"(c[3])
        : "r"(a[0]), "r"(a[1]), "r"(a[2]), "r"(a[3]), "r"(b0), "r"(b1));
}
__device__ __forceinline__ void ldsm_x4(uint32_t& r0, uint32_t& r1, uint32_t& r2, uint32_t& r3,
                                        uint32_t a) {
    asm volatile("ldmatrix.sync.aligned.m8n8.x4.shared.b16 {%0,%1,%2,%3}, [%4];"
                 : "=r"(r0), "=r"(r1), "=r"(r2), "=r"(r3) : "r"(a));
}
__device__ __forceinline__ void cp_async16(uint32_t dst, const void* src) {
    asm volatile("cp.async.cg.shared.global [%0], [%1], 16;" :: "r"(dst), "l"(src) : "memory");
}
__device__ __forceinline__ void cp_commit() { asm volatile("cp.async.commit_group;" ::: "memory"); }
__device__ __forceinline__ void cp_wait0()  { asm volatile("cp.async.wait_group 0;" ::: "memory"); }
__device__ __forceinline__ void cp_wait1()  { asm volatile("cp.async.wait_group 1;" ::: "memory"); }
__device__ __forceinline__ void cp_wait2()  { asm volatile("cp.async.wait_group 2;" ::: "memory"); }

// ---------------- Psi MLP layers 1-2 only: h2 (32) + ones column, transposed ----------------
__global__ void psi2_kernel(const float* __restrict__ xs, const float* __restrict__ vs,
                            const float* __restrict__ W1, const float* __restrict__ b1,
                            const float* __restrict__ W2, const float* __restrict__ b2)
{
    __shared__ float sW1[128];
    __shared__ float sb1[64];
    __shared__ float sW2[64 * 32];
    __shared__ float sb2[32];

    int tid = threadIdx.x;
    for (int i = tid; i < 128; i += 256)      sW1[i] = W1[i];
    for (int i = tid; i < 64; i += 256)       sb1[i] = b1[i];
    for (int i = tid; i < 64 * 32; i += 256)  sW2[i] = W2[i];
    if (tid < 32)                             sb2[tid] = b2[tid];
    __syncthreads();

    int p = blockIdx.x * 256 + tid;
    int v = p >> 9;
    int x = p & 511;
    float xin = xs[x];
    float vin = vs[v];

    float h1[64];
#pragma unroll
    for (int j = 0; j < 64; j++) {
        float s = fmaf(xin, sW1[j], fmaf(vin, sW1[64 + j], sb1[j]));
        h1[j] = fmaxf(s, 0.0f);
    }
#pragma unroll
    for (int j = 0; j < 32; j++) {
        float s = sb2[j];
#pragma unroll
        for (int i = 0; i < 64; i++) s = fmaf(h1[i], sW2[i * 32 + j], s);
        g_h2T[(size_t)j * NVX + p] = __uint_as_float(rna_tf32(fmaxf(s, 0.0f)));
    }
    g_h2T[(size_t)32 * NVX + p] = 1.0f;
#pragma unroll
    for (int j = 33; j < NH; j++)
        g_h2T[(size_t)j * NVX + p] = 0.0f;
}

// ---------------- zero g_w2 ----------------
__global__ void zero_w2_kernel()
{
    int i = blockIdx.x * 256 + threadIdx.x;
    if (i < NT * NH) g_w2[i] = 0.0f;
}

// ---------------- phi table transposed: [Nx_out][KP], tf32-rounded, pad zeros ----------------
__global__ void phi_kernel(const float* __restrict__ x_out, const float* __restrict__ xs)
{
    int idx = blockIdx.x * 256 + threadIdx.x;
    if (idx >= NXOUT * KP) return;
    int n = idx / KP;
    int k = idx - n * KP;
    float val = 0.0f;
    if (k < KDIM) {
        float w = (2.0f * 3.14159265358979323846f) / (xs[NXS - 1] - xs[0]);
        float xo = x_out[n];
        if (k < 128) val = sinf((float)(k + 1) * w * xo);
        else         val = cosf((float)(k - 128) * w * xo);
        val = __uint_as_float(rna_tf32(val));
    }
    g_phiT[idx] = val;
}

// ---------------- GEMM1b: g_w2 (1024x48) += f (1024x65536) @ h2T^T ----------------
// CTA tile 128x48, BK=32, 4-stage cp.async (loads issued before compute), 192 threads.
// Warps 2(M) x 3(N), warp tile 64x16. Split-K 36 (32 x 57 + 4 x 56 iters), grid (1,8,36).
#define B1_BM 128
#define B1_BN 48
#define B1_BK 32
#define B1_THREADS 192
#define B1_SPLITS 36
#define B1_SA 36                 // bank pattern (4r+4o)%32 within row groups -> conflict-free
#define B1_A_FLOATS (B1_BM * B1_SA)     // 4608
#define B1_B_FLOATS (B1_BN * B1_SA)     // 1728
#define B1_STAGE (B1_A_FLOATS + B1_B_FLOATS)   // 6336
#define B1_NSTAGE 4
#define B1_SMEM_FLOATS (B1_NSTAGE * B1_STAGE)  // 25344 floats = 101376 B
#define B1_A_VEC (B1_BM * 8)     // 1024 float4 per A tile
#define B1_B_VEC (B1_BN * 8)     // 384 float4 per B tile

__global__ void __launch_bounds__(B1_THREADS, 2) gemm1b(const float* __restrict__ f)
{
    extern __shared__ __align__(16) float sm[];
    uint32_t sm_b = smem_u32(sm);

    const int tid = threadIdx.x;
    const int lane = tid & 31;
    const int warp = tid >> 5;               // 0..5
    const int wm = warp & 1;                 // 0..1 (M)
    const int wn = warp >> 1;                // 0..2 (N)
    const int q = lane >> 2, j = lane & 3;

    const int row0 = blockIdx.y * B1_BM;
    const int z = blockIdx.z;
    int it0, nit;
    if (z < 32) { it0 = z * 57;                  nit = 57; }
    else        { it0 = 32 * 57 + (z - 32) * 56; nit = 56; }
    const size_t kb0 = (size_t)it0 * B1_BK;

    float acc[4][2][4];
#pragma unroll
    for (int a = 0; a < 4; a++)
#pragma unroll
        for (int b = 0; b < 2; b++)
#pragma unroll
            for (int c = 0; c < 4; c++) acc[a][b][c] = 0.0f;

    uint32_t a_u32[B1_NSTAGE], b_u32[B1_NSTAGE];
#pragma unroll
    for (int s = 0; s < B1_NSTAGE; s++) {
        a_u32[s] = sm_b + (uint32_t)(s * B1_STAGE) * 4u;
        b_u32[s] = a_u32[s] + (uint32_t)B1_A_FLOATS * 4u;
    }

    // ldmatrix lane offsets
    const int arow = (lane & 7) + ((lane >> 3) & 1) * 8;
    const int acol = (lane >> 4) * 4;
    uint32_t offA[4];
#pragma unroll
    for (int mt = 0; mt < 4; mt++)
        offA[mt] = (uint32_t)(((wm * 64 + mt * 16 + arow) * B1_SA + acol) * 4);

    const int brow = (lane & 7);
    const int bsel = (lane >> 4);
    const int bcol = ((lane >> 3) & 1) * 4;
    const uint32_t offB = (uint32_t)(((wn * 16 + bsel * 8 + brow) * B1_SA + bcol) * 4);

    auto load_stage = [&](int s, size_t kb) {
        // A: 1024 float4 over 192 threads
        for (int idx = tid; idx < B1_A_VEC; idx += B1_THREADS) {
            int r = idx >> 3, o = idx & 7;
            cp_async16(a_u32[s] + (uint32_t)(r * B1_SA + o * 4) * 4,
                       f + (size_t)(row0 + r) * NVX + kb + o * 4);
        }
        // B: 384 float4 = 2/thread
#pragma unroll
        for (int p = 0; p < 2; p++) {
            int idx = tid + p * B1_THREADS;
            int r = idx >> 3, o = idx & 7;
            cp_async16(b_u32[s] + (uint32_t)(r * B1_SA + o * 4) * 4,
                       g_h2T + (size_t)r * NVX + kb + o * 4);
        }
        cp_commit();
    };

    // prologue: 3 stages in flight
    load_stage(0, kb0);
    load_stage(1, kb0 + B1_BK);
    load_stage(2, kb0 + 2 * B1_BK);

    for (int it = 0; it < nit; ++it) {
        const int s = it & 3;
        if (it < nit - 2) cp_wait2();
        else if (it == nit - 2) cp_wait1();
        else cp_wait0();
        __syncthreads();   // stage s ready for all; stage (it-1)&3 = (it+3)&3 free

        // issue next loads BEFORE compute so DRAM stays fed during the MMA burst
        if (it + 3 < nit)
            load_stage((s + 3) & 3, kb0 + (size_t)(it + 3) * B1_BK);

        const uint32_t aS = a_u32[s];
        const uint32_t bS = b_u32[s];
#pragma unroll
        for (int kk = 0; kk < 4; kk++) {
            uint32_t afr[4][4];
#pragma unroll
            for (int mt = 0; mt < 4; mt++)
                ldsm_x4(afr[mt][0], afr[mt][1], afr[mt][2], afr[mt][3],
                        aS + offA[mt] + kk * 32);
            uint32_t bfr[2][2];
            ldsm_x4(bfr[0][0], bfr[0][1], bfr[1][0], bfr[1][1], bS + offB + kk * 32);
#pragma unroll
            for (int nt = 0; nt < 2; nt++)
#pragma unroll
                for (int mt = 0; mt < 4; mt++)
                    mma_tf32(acc[mt][nt], afr[mt], bfr[nt][0], bfr[nt][1]);
        }
    }

    // atomic accumulate into g_w2
#pragma unroll
    for (int mt = 0; mt < 4; mt++) {
        int r0 = row0 + wm * 64 + mt * 16 + q;
#pragma unroll
        for (int nt = 0; nt < 2; nt++) {
            int c0 = wn * 16 + nt * 8 + 2 * j;
            atomicAdd(&g_w2[r0 * NH + c0],           acc[mt][nt][0]);
            atomicAdd(&g_w2[r0 * NH + c0 + 1],       acc[mt][nt][1]);
            atomicAdd(&g_w2[(r0 + 8) * NH + c0],     acc[mt][nt][2]);
            atomicAdd(&g_w2[(r0 + 8) * NH + c0 + 1], acc[mt][nt][3]);
        }
    }
}

// ---------------- small gemm: g_w (1024x288, pad zeros) = scale * g_w2 @ [W3; b3] ----------------
__global__ void small_gemm(const float* __restrict__ xs, const float* __restrict__ vs,
                           const float* __restrict__ W3, const float* __restrict__ b3)
{
    __shared__ float sa[33];
    int t = blockIdx.x;
    int tid = threadIdx.x;
    if (tid < 33) sa[tid] = g_w2[t * NH + tid];
    __syncthreads();
    float scale = (xs[1] - xs[0]) * (vs[1] - vs[0]);   // hx * hv
    for (int k = tid; k < KP; k += 256) {
        float s = 0.0f;
        if (k < KDIM) {
            s = sa[32] * b3[k];
#pragma unroll
            for (int jj = 0; jj < 32; jj++) s = fmaf(sa[jj], W3[jj * KDIM + k], s);
            s *= scale;
        }
        g_w[(size_t)t * KP + k] = s;
    }
}

// ---------------- GEMM2 via mma.sync tf32: out = g_w (1024x288) @ phiT^T (288x2048) ----------
#define BK 32
#define G2M 64
#define G2N 256
#define G2_AST 292
#define G2_SB 36
#define G2_A_FLOATS (G2M * G2_AST)                 // 18688
#define G2_B_STAGE (G2N * G2_SB)                   // 9216
#define G2_SMEM_FLOATS (G2_A_FLOATS + 3 * G2_B_STAGE)   // 46336 floats = 185344 B

__global__ void __launch_bounds__(256, 1) gemm2_mma(float* __restrict__ out)
{
    extern __shared__ __align__(16) float sm[];
    uint32_t sm_b = smem_u32(sm);

    const int tid = threadIdx.x;
    const int lane = tid & 31;
    const int warp = tid >> 5;
    const int wm = warp & 1;
    const int wn = warp >> 1;
    const int q = lane >> 2, j = lane & 3;

    const int row0 = blockIdx.y * G2M;
    const int col0 = blockIdx.x * G2N;

    uint32_t b_u32[3];
#pragma unroll
    for (int s = 0; s < 3; s++)
        b_u32[s] = sm_b + (uint32_t)(G2_A_FLOATS + s * G2_B_STAGE) * 4u;

    for (int idx = tid; idx < G2M * 72; idx += 256) {
        int r = idx / 72, c = idx - (idx / 72) * 72;
        float4 v = *(const float4*)(g_w + (size_t)(row0 + r) * KP + c * 4);
        uint4 u;
        u.x = rna_tf32(v.x); u.y = rna_tf32(v.y); u.z = rna_tf32(v.z); u.w = rna_tf32(v.w);
        *(uint4*)(sm + r * G2_AST + c * 4) = u;
    }

    auto load_b = [&](int s, int k0) {
#pragma unroll
        for (int p = 0; p < 8; p++) {
            int idx = tid + p * 256;
            int r = idx >> 3, o = idx & 7;
            cp_async16(b_u32[s] + (uint32_t)(r * G2_SB + o * 4) * 4,
                       g_phiT + (size_t)(col0 + r) * KP + k0 + o * 4);
        }
        cp_commit();
    };
    load_b(0, 0);
    load_b(1, BK);

    const int arow = (lane & 7) + ((lane >> 3) & 1) * 8;
    const int acol = (lane >> 4) * 4;
    uint32_t offA[2];
#pragma unroll
    for (int mt = 0; mt < 2; mt++)
        offA[mt] = (uint32_t)(((wm * 32 + mt * 16 + arow) * G2_AST + acol) * 4);

    const int brow = (lane & 7);
    const int bsel = (lane >> 4);
    const int bcol = ((lane >> 3) & 1) * 4;
    uint32_t offB[4];
#pragma unroll
    for (int p = 0; p < 4; p++)
        offB[p] = (uint32_t)(((wn * 64 + (2 * p + bsel) * 8 + brow) * G2_SB + bcol) * 4);

    float acc[2][8][4];
#pragma unroll
    for (int a = 0; a < 2; a++)
#pragma unroll
        for (int b = 0; b < 8; b++)
#pragma unroll
            for (int c = 0; c < 4; c++) acc[a][b][c] = 0.0f;

    const int NIT2 = KP / BK;   // 9
    for (int it = 0; it < NIT2; ++it) {
        const int s = it % 3;
        if (it < NIT2 - 1) cp_wait1(); else cp_wait0();
        __syncthreads();

        if (it + 2 < NIT2) load_b((s + 2) % 3, (it + 2) * BK);

        const uint32_t bS = b_u32[s];
        const uint32_t kbase = (uint32_t)(it * BK) * 4u;
#pragma unroll
        for (int kk = 0; kk < 4; kk++) {
            uint32_t afr[2][4];
#pragma unroll
            for (int mt = 0; mt < 2; mt++)
                ldsm_x4(afr[mt][0], afr[mt][1], afr[mt][2], afr[mt][3],
                        sm_b + offA[mt] + kbase + kk * 32);
            uint32_t bfr[8][2];
#pragma unroll
            for (int p = 0; p < 4; p++)
                ldsm_x4(bfr[2 * p][0], bfr[2 * p][1], bfr[2 * p + 1][0], bfr[2 * p + 1][1],
                        bS + offB[p] + kk * 32);
#pragma unroll
            for (int nt = 0; nt < 8; nt++)
#pragma unroll
                for (int mt = 0; mt < 2; mt++)
                    mma_tf32(acc[mt][nt], afr[mt], bfr[nt][0], bfr[nt][1]);
        }
    }

#pragma unroll
    for (int mt = 0; mt < 2; mt++) {
        int r0 = row0 + wm * 32 + mt * 16 + q;
#pragma unroll
        for (int nt = 0; nt < 8; nt++) {
            int c0 = col0 + wn * 64 + nt * 8 + 2 * j;
            *(float2*)&out[(size_t)r0 * NXOUT + c0]       = make_float2(acc[mt][nt][0], acc[mt][nt][1]);
            *(float2*)&out[(size_t)(r0 + 8) * NXOUT + c0] = make_float2(acc[mt][nt][2], acc[mt][nt][3]);
        }
    }
}

extern "C" void kernel_launch(void* const* d_in, const int* in_sizes, int n_in,
                              void* d_out, int out_size)
{
    const float* x_out = (const float*)d_in[0];
    const float* f     = (const float*)d_in[1];
    const float* xs    = (const float*)d_in[2];
    const float* vs    = (const float*)d_in[3];
    const float* W1    = (const float*)d_in[4];
    const float* b1    = (const float*)d_in[5];
    const float* W2    = (const float*)d_in[6];
    const float* b2    = (const float*)d_in[7];
    const float* W3    = (const float*)d_in[8];
    const float* b3    = (const float*)d_in[9];
    float* out = (float*)d_out;

    static int smem_set = 0;
    if (!smem_set) {
        cudaFuncSetAttribute(gemm1b, cudaFuncAttributeMaxDynamicSharedMemorySize,
                             B1_SMEM_FLOATS * 4);
        cudaFuncSetAttribute(gemm2_mma, cudaFuncAttributeMaxDynamicSharedMemorySize,
                             G2_SMEM_FLOATS * 4);
        smem_set = 1;
    }

    psi2_kernel<<<NVX / 256, 256>>>(xs, vs, W1, b1, W2, b2);
    zero_w2_kernel<<<(NT * NH + 255) / 256, 256>>>();
    phi_kernel<<<(NXOUT * KP + 255) / 256, 256>>>(x_out, xs);
    {
        dim3 grid(1, NT / B1_BM, B1_SPLITS);   // 1 x 8 x 36 = 288 CTAs
        gemm1b<<<grid, B1_THREADS, B1_SMEM_FLOATS * 4>>>(f);
    }
    small_gemm<<<NT, 256>>>(xs, vs, W3, b3);
    {
        dim3 grid(NXOUT / G2N, NT / G2M);
        gemm2_mma<<<grid, 256, G2_SMEM_FLOATS * 4>>>(out);
    }
}

// round 14
// speedup vs baseline: 1.0041x; 1.0041x over previous
#include <cuda_runtime.h>
#include <math.h>
#include <stdint.h>

#define NT 1024
#define NV 128
#define NXS 512
#define NVX 65536          // NV*NXS (contraction length of GEMM1)
#define KDIM 257
#define KP 288             // padded KDIM
#define NXOUT 2048
#define NH 48              // padded hidden+1 (33 -> 48)

// -------- scratch (no allocations allowed) --------
__device__ float g_h2T[(size_t)NH * NVX];      // [j][p]: relu layer-2 (j<32), ones (j=32), 0 pad
__device__ float g_w2[(size_t)NT * NH];        // f @ [H2|1]  (1024 x 48)
__device__ float g_phiT[(size_t)NXOUT * KP];   // fourier basis transposed [n][k], tf32-rounded

// ============================ helpers ============================
__device__ __forceinline__ uint32_t smem_u32(const void* p) {
    uint32_t a;
    asm("{ .reg .u64 t; cvta.to.shared.u64 t, %1; cvt.u32.u64 %0, t; }" : "=r"(a) : "l"(p));
    return a;
}
__device__ __forceinline__ uint32_t rna_tf32(float x) {
    uint32_t r;
    asm("cvt.rna.tf32.f32 %0, %1;" : "=r"(r) : "f"(x));
    return r;
}
__device__ __forceinline__ void mma_tf32(float* c, const uint32_t* a, uint32_t b0, uint32_t b1) {
    asm volatile(
        "mma.sync.aligned.m16n8k8.row.col.f32.tf32.tf32.f32 "
        "{%0,%1,%2,%3}, {%4,%5,%6,%7}, {%8,%9}, {%0,%1,%2,%3};"
        : "+f"(c[0]), "+f"(c[1]), "+f"(c[2]), "+f"(c[3])
        : "r"(a[0]), "r"(a[1]), "r"(a[2]), "r"(a[3]), "r"(b0), "r"(b1));
}
__device__ __forceinline__ void ldsm_x4(uint32_t& r0, uint32_t& r1, uint32_t& r2, uint32_t& r3,
                                        uint32_t a) {
    asm volatile("ldmatrix.sync.aligned.m8n8.x4.shared.b16 {%0,%1,%2,%3}, [%4];"
                 : "=r"(r0), "=r"(r1), "=r"(r2), "=r"(r3) : "r"(a));
}
__device__ __forceinline__ void cp_async16(uint32_t dst, const void* src) {
    asm volatile("cp.async.cg.shared.global [%0], [%1], 16;" :: "r"(dst), "l"(src) : "memory");
}
__device__ __forceinline__ void cp_commit() { asm volatile("cp.async.commit_group;" ::: "memory"); }
__device__ __forceinline__ void cp_wait0()  { asm volatile("cp.async.wait_group 0;" ::: "memory"); }
__device__ __forceinline__ void cp_wait1()  { asm volatile("cp.async.wait_group 1;" ::: "memory"); }

// ---------------- Psi MLP layers 1-2 only: h2 (32) + ones column, transposed ----------------
__global__ void psi2_kernel(const float* __restrict__ xs, const float* __restrict__ vs,
                            const float* __restrict__ W1, const float* __restrict__ b1,
                            const float* __restrict__ W2, const float* __restrict__ b2)
{
    __shared__ float sW1[128];
    __shared__ float sb1[64];
    __shared__ float sW2[64 * 32];
    __shared__ float sb2[32];

    int tid = threadIdx.x;
    for (int i = tid; i < 128; i += 256)      sW1[i] = W1[i];
    for (int i = tid; i < 64; i += 256)       sb1[i] = b1[i];
    for (int i = tid; i < 64 * 32; i += 256)  sW2[i] = W2[i];
    if (tid < 32)                             sb2[tid] = b2[tid];
    __syncthreads();

    int p = blockIdx.x * 256 + tid;
    int v = p >> 9;
    int x = p & 511;
    float xin = xs[x];
    float vin = vs[v];

    float h1[64];
#pragma unroll
    for (int j = 0; j < 64; j++) {
        float s = fmaf(xin, sW1[j], fmaf(vin, sW1[64 + j], sb1[j]));
        h1[j] = fmaxf(s, 0.0f);
    }
#pragma unroll
    for (int j = 0; j < 32; j++) {
        float s = sb2[j];
#pragma unroll
        for (int i = 0; i < 64; i++) s = fmaf(h1[i], sW2[i * 32 + j], s);
        g_h2T[(size_t)j * NVX + p] = __uint_as_float(rna_tf32(fmaxf(s, 0.0f)));
    }
    g_h2T[(size_t)32 * NVX + p] = 1.0f;
#pragma unroll
    for (int j = 33; j < NH; j++)
        g_h2T[(size_t)j * NVX + p] = 0.0f;
}

// ---------------- phi table transposed + zero g_w2 (fused) ----------------
__global__ void phi_kernel(const float* __restrict__ x_out, const float* __restrict__ xs)
{
    int idx = blockIdx.x * 256 + threadIdx.x;
    if (idx < NT * NH) g_w2[idx] = 0.0f;
    if (idx >= NXOUT * KP) return;
    int n = idx / KP;
    int k = idx - n * KP;
    float val = 0.0f;
    if (k < KDIM) {
        float w = (2.0f * 3.14159265358979323846f) / (xs[NXS - 1] - xs[0]);
        float xo = x_out[n];
        if (k < 128) val = sinf((float)(k + 1) * w * xo);
        else         val = cosf((float)(k - 128) * w * xo);
        val = __uint_as_float(rna_tf32(val));
    }
    g_phiT[idx] = val;
}

// ---------------- GEMM1b: g_w2 (1024x48) += f (1024x65536) @ h2T^T ----------------
// (R12 config) CTA tile 128x48, BK=64, 192 threads: warps 2(M) x 3(N), warp tile 64x16.
// Split-K 36 (16 x 29 iters + 20 x 28 iters of BK=64), grid (1, 8, 36) = 288 CTAs, 2/SM.
#define B1_BM 128
#define B1_BN 48
#define B1_BK 64
#define B1_THREADS 192
#define B1_SPLITS 36
#define B1_SA 68                 // bank pattern (4r+j)%32 -> conflict-free ldmatrix
#define B1_A_FLOATS (B1_BM * B1_SA)     // 8704
#define B1_B_FLOATS (B1_BN * B1_SA)     // 3264
#define B1_STAGE (B1_A_FLOATS + B1_B_FLOATS)   // 11968
#define B1_SMEM_FLOATS (2 * B1_STAGE)          // 23936 floats = 95744 B

__global__ void __launch_bounds__(B1_THREADS, 2) gemm1b(const float* __restrict__ f)
{
    extern __shared__ __align__(16) float sm[];
    uint32_t sm_b = smem_u32(sm);

    const int tid = threadIdx.x;
    const int lane = tid & 31;
    const int warp = tid >> 5;               // 0..5
    const int wm = warp & 1;                 // 0..1 (M)
    const int wn = warp >> 1;                // 0..2 (N)
    const int q = lane >> 2, j = lane & 3;

    const int row0 = blockIdx.y * B1_BM;
    const int z = blockIdx.z;
    int it0, nit;
    if (z < 16) { it0 = z * 29;               nit = 29; }
    else        { it0 = 16 * 29 + (z - 16) * 28; nit = 28; }
    const size_t kb0 = (size_t)it0 * B1_BK;

    float acc[4][2][4];
#pragma unroll
    for (int a = 0; a < 4; a++)
#pragma unroll
        for (int b = 0; b < 2; b++)
#pragma unroll
            for (int c = 0; c < 4; c++) acc[a][b][c] = 0.0f;

    uint32_t a_u32[2], b_u32[2];
#pragma unroll
    for (int s = 0; s < 2; s++) {
        a_u32[s] = sm_b + (uint32_t)(s * B1_STAGE) * 4u;
        b_u32[s] = a_u32[s] + (uint32_t)B1_A_FLOATS * 4u;
    }

    const int arow = (lane & 7) + ((lane >> 3) & 1) * 8;
    const int acol = (lane >> 4) * 4;
    uint32_t offA[4];
#pragma unroll
    for (int mt = 0; mt < 4; mt++)
        offA[mt] = (uint32_t)(((wm * 64 + mt * 16 + arow) * B1_SA + acol) * 4);

    const int brow = (lane & 7);
    const int bsel = (lane >> 4);
    const int bcol = ((lane >> 3) & 1) * 4;
    const uint32_t offB = (uint32_t)(((wn * 16 + bsel * 8 + brow) * B1_SA + bcol) * 4);

    auto load_stage = [&](int s, size_t kb) {
        for (int idx = tid; idx < B1_BM * 16; idx += B1_THREADS) {
            int r = idx >> 4, o = idx & 15;
            cp_async16(a_u32[s] + (uint32_t)(r * B1_SA + o * 4) * 4,
                       f + (size_t)(row0 + r) * NVX + kb + o * 4);
        }
#pragma unroll
        for (int p = 0; p < 4; p++) {
            int idx = tid + p * B1_THREADS;
            int r = idx >> 4, o = idx & 15;
            cp_async16(b_u32[s] + (uint32_t)(r * B1_SA + o * 4) * 4,
                       g_h2T + (size_t)r * NVX + kb + o * 4);
        }
        cp_commit();
    };

    load_stage(0, kb0);
    load_stage(1, kb0 + B1_BK);

    for (int it = 0; it < nit; ++it) {
        const int s = it & 1;
        if (it + 1 < nit) cp_wait1(); else cp_wait0();
        __syncthreads();

        const uint32_t aS = a_u32[s];
        const uint32_t bS = b_u32[s];
#pragma unroll
        for (int kk = 0; kk < 8; kk++) {
            uint32_t afr[4][4];
#pragma unroll
            for (int mt = 0; mt < 4; mt++)
                ldsm_x4(afr[mt][0], afr[mt][1], afr[mt][2], afr[mt][3],
                        aS + offA[mt] + kk * 32);
            uint32_t bfr[2][2];
            ldsm_x4(bfr[0][0], bfr[0][1], bfr[1][0], bfr[1][1], bS + offB + kk * 32);
#pragma unroll
            for (int nt = 0; nt < 2; nt++)
#pragma unroll
                for (int mt = 0; mt < 4; mt++)
                    mma_tf32(acc[mt][nt], afr[mt], bfr[nt][0], bfr[nt][1]);
        }
        __syncthreads();
        if (it + 2 < nit)
            load_stage(s, kb0 + (size_t)(it + 2) * B1_BK);
    }

    // atomic accumulate into g_w2
#pragma unroll
    for (int mt = 0; mt < 4; mt++) {
        int r0 = row0 + wm * 64 + mt * 16 + q;
#pragma unroll
        for (int nt = 0; nt < 2; nt++) {
            int c0 = wn * 16 + nt * 8 + 2 * j;
            atomicAdd(&g_w2[r0 * NH + c0],           acc[mt][nt][0]);
            atomicAdd(&g_w2[r0 * NH + c0 + 1],       acc[mt][nt][1]);
            atomicAdd(&g_w2[(r0 + 8) * NH + c0],     acc[mt][nt][2]);
            atomicAdd(&g_w2[(r0 + 8) * NH + c0 + 1], acc[mt][nt][3]);
        }
    }
}

// ---------------- GEMM2 fused: out = [scale*(g_w2 @ [W3;b3])] @ phiT^T ----------------
// CTA tile 64(M) x 256(N). A (64x288) computed IN-KERNEL from g_w2 (64x33) and W3/b3,
// rna-rounded into smem; B (phiT) 2-stage cp.async; 9 K-iters of BK=32.
#define BK 32
#define G2M 64
#define G2N 256
#define G2_AST 292
#define G2_SB 36
#define G2_A_FLOATS (G2M * G2_AST)                 // 18688
#define G2_W3_OFF G2_A_FLOATS                      // sw3: 33 x 288 = 9504 floats
#define G2_W2_OFF (G2_W3_OFF + 33 * 288)           // sw2: 64 x 36 = 2304 floats
#define G2_B_OFF  (G2_W2_OFF + 64 * 36)            // 30496 floats (16B aligned: x4 = 121984)
#define G2_B_STAGE (G2N * G2_SB)                   // 9216
#define G2_SMEM_FLOATS (G2_B_OFF + 2 * G2_B_STAGE) // 48928 floats = 195712 B

__global__ void __launch_bounds__(256, 1) gemm2_mma(float* __restrict__ out,
                                                    const float* __restrict__ xs,
                                                    const float* __restrict__ vs,
                                                    const float* __restrict__ W3,
                                                    const float* __restrict__ b3)
{
    extern __shared__ __align__(16) float sm[];
    uint32_t sm_b = smem_u32(sm);

    const int tid = threadIdx.x;
    const int lane = tid & 31;
    const int warp = tid >> 5;               // 0..7
    const int wm = warp & 1;
    const int wn = warp >> 1;
    const int q = lane >> 2, j = lane & 3;

    const int row0 = blockIdx.y * G2M;
    const int col0 = blockIdx.x * G2N;

    float* sw3 = sm + G2_W3_OFF;             // [33][288]
    float* sw2 = sm + G2_W2_OFF;             // [64][36]

    uint32_t b_u32[2];
#pragma unroll
    for (int s = 0; s < 2; s++)
        b_u32[s] = sm_b + (uint32_t)(G2_B_OFF + s * G2_B_STAGE) * 4u;

    // ---- kick off B stage 0/1 loads first (DRAM/L2 latency overlap with A compute) ----
    auto load_b = [&](int s, int k0) {
#pragma unroll
        for (int p = 0; p < 8; p++) {
            int idx = tid + p * 256;
            int r = idx >> 3, o = idx & 7;
            cp_async16(b_u32[s] + (uint32_t)(r * G2_SB + o * 4) * 4,
                       g_phiT + (size_t)(col0 + r) * KP + k0 + o * 4);
        }
        cp_commit();
    };
    load_b(0, 0);
    load_b(1, BK);

    // ---- stage W3 (32x257) + b3 into sw3[33][288], pad zeros ----
    for (int idx = tid; idx < 32 * 288; idx += 256) {
        int jr = idx / 288, c = idx - (idx / 288) * 288;
        sw3[idx] = (c < KDIM) ? W3[jr * KDIM + c] : 0.0f;
    }
    for (int c = tid; c < 288; c += 256)
        sw3[32 * 288 + c] = (c < KDIM) ? b3[c] : 0.0f;
    // ---- stage w2 rows ----
    for (int idx = tid; idx < G2M * 33; idx += 256) {
        int r = idx / 33, jj = idx - (idx / 33) * 33;
        sw2[r * 36 + jj] = g_w2[(row0 + r) * NH + jj];
    }
    __syncthreads();

    // ---- compute A = rna(scale * w2 @ [W3;b3]) into smem staging ----
    {
        float scale = (xs[1] - xs[0]) * (vs[1] - vs[0]);   // hx * hv
        // warp w owns rows w*8..w*8+7; lane owns cols lane + 32m (m=0..8)
#pragma unroll
        for (int rr = 0; rr < 8; rr++) {
            int r = warp * 8 + rr;
            const float* w2r = sw2 + r * 36;
            float a[9];
#pragma unroll
            for (int m = 0; m < 9; m++) a[m] = 0.0f;
            for (int jj = 0; jj < 33; jj++) {
                float wv = w2r[jj];
                const float* w3r = sw3 + jj * 288 + lane;
#pragma unroll
                for (int m = 0; m < 9; m++)
                    a[m] = fmaf(wv, w3r[m * 32], a[m]);
            }
            float* dst = sm + r * G2_AST + lane;
#pragma unroll
            for (int m = 0; m < 9; m++)
                dst[m * 32] = __uint_as_float(rna_tf32(scale * a[m]));
        }
    }

    // ldmatrix offsets
    const int arow = (lane & 7) + ((lane >> 3) & 1) * 8;
    const int acol = (lane >> 4) * 4;
    uint32_t offA[2];
#pragma unroll
    for (int mt = 0; mt < 2; mt++)
        offA[mt] = (uint32_t)(((wm * 32 + mt * 16 + arow) * G2_AST + acol) * 4);

    const int brow = (lane & 7);
    const int bsel = (lane >> 4);
    const int bcol = ((lane >> 3) & 1) * 4;
    uint32_t offB[4];
#pragma unroll
    for (int p = 0; p < 4; p++)
        offB[p] = (uint32_t)(((wn * 64 + (2 * p + bsel) * 8 + brow) * G2_SB + bcol) * 4);

    float acc[2][8][4];
#pragma unroll
    for (int a = 0; a < 2; a++)
#pragma unroll
        for (int b = 0; b < 8; b++)
#pragma unroll
            for (int c = 0; c < 4; c++) acc[a][b][c] = 0.0f;

    const int NIT2 = KP / BK;   // 9
    for (int it = 0; it < NIT2; ++it) {
        const int s = it & 1;
        if (it + 1 < NIT2) cp_wait1(); else cp_wait0();
        __syncthreads();        // B stage s ready; A staging visible (first iter)

        const uint32_t bS = b_u32[s];
        const uint32_t kbase = (uint32_t)(it * BK) * 4u;
#pragma unroll
        for (int kk = 0; kk < 4; kk++) {
            uint32_t afr[2][4];
#pragma unroll
            for (int mt = 0; mt < 2; mt++)
                ldsm_x4(afr[mt][0], afr[mt][1], afr[mt][2], afr[mt][3],
                        sm_b + offA[mt] + kbase + kk * 32);
            uint32_t bfr[8][2];
#pragma unroll
            for (int p = 0; p < 4; p++)
                ldsm_x4(bfr[2 * p][0], bfr[2 * p][1], bfr[2 * p + 1][0], bfr[2 * p + 1][1],
                        bS + offB[p] + kk * 32);
#pragma unroll
            for (int nt = 0; nt < 8; nt++)
#pragma unroll
                for (int mt = 0; mt < 2; mt++)
                    mma_tf32(acc[mt][nt], afr[mt], bfr[nt][0], bfr[nt][1]);
        }
        __syncthreads();        // stage s consumed before refill
        if (it + 2 < NIT2) load_b(s, (it + 2) * BK);
    }

#pragma unroll
    for (int mt = 0; mt < 2; mt++) {
        int r0 = row0 + wm * 32 + mt * 16 + q;
#pragma unroll
        for (int nt = 0; nt < 8; nt++) {
            int c0 = col0 + wn * 64 + nt * 8 + 2 * j;
            *(float2*)&out[(size_t)r0 * NXOUT + c0]       = make_float2(acc[mt][nt][0], acc[mt][nt][1]);
            *(float2*)&out[(size_t)(r0 + 8) * NXOUT + c0] = make_float2(acc[mt][nt][2], acc[mt][nt][3]);
        }
    }
}

extern "C" void kernel_launch(void* const* d_in, const int* in_sizes, int n_in,
                              void* d_out, int out_size)
{
    const float* x_out = (const float*)d_in[0];
    const float* f     = (const float*)d_in[1];
    const float* xs    = (const float*)d_in[2];
    const float* vs    = (const float*)d_in[3];
    const float* W1    = (const float*)d_in[4];
    const float* b1    = (const float*)d_in[5];
    const float* W2    = (const float*)d_in[6];
    const float* b2    = (const float*)d_in[7];
    const float* W3    = (const float*)d_in[8];
    const float* b3    = (const float*)d_in[9];
    float* out = (float*)d_out;

    static int smem_set = 0;
    if (!smem_set) {
        cudaFuncSetAttribute(gemm1b, cudaFuncAttributeMaxDynamicSharedMemorySize,
                             B1_SMEM_FLOATS * 4);
        cudaFuncSetAttribute(gemm2_mma, cudaFuncAttributeMaxDynamicSharedMemorySize,
                             G2_SMEM_FLOATS * 4);
        smem_set = 1;
    }

    psi2_kernel<<<NVX / 256, 256>>>(xs, vs, W1, b1, W2, b2);
    phi_kernel<<<(NXOUT * KP + 255) / 256, 256>>>(x_out, xs);
    {
        dim3 grid(1, NT / B1_BM, B1_SPLITS);   // 1 x 8 x 36 = 288 CTAs
        gemm1b<<<grid, B1_THREADS, B1_SMEM_FLOATS * 4>>>(f);
    }
    {
        dim3 grid(NXOUT / G2N, NT / G2M);
        gemm2_mma<<<grid, 256, G2_SMEM_FLOATS * 4>>>(out, xs, vs, W3, b3);
    }
}

// round 15
// speedup vs baseline: 1.1033x; 1.0988x over previous
#include <cuda_runtime.h>
#include <math.h>
#include <stdint.h>

#define NT 1024
#define NV 128
#define NXS 512
#define NVX 65536          // NV*NXS (contraction length of GEMM1)
#define KDIM 257
#define KP 288             // padded KDIM
#define NXOUT 2048
#define NH 48              // padded hidden+1 (33 -> 48)

// -------- scratch (no allocations allowed) --------
__device__ float g_h2T[(size_t)NH * NVX];      // [j][p]: relu layer-2 (j<32), ones (j=32), 0 pad
__device__ float g_w2[(size_t)NT * NH];        // f @ [H2|1]  (1024 x 48)
__device__ float g_w[(size_t)NT * KP];         // scale*(w2@[W3;b3]), rna-rounded (1024 x 288)
__device__ float g_phiT[(size_t)NXOUT * KP];   // fourier basis transposed [n][k], tf32-rounded

// ============================ helpers ============================
__device__ __forceinline__ uint32_t smem_u32(const void* p) {
    uint32_t a;
    asm("{ .reg .u64 t; cvta.to.shared.u64 t, %1; cvt.u32.u64 %0, t; }" : "=r"(a) : "l"(p));
    return a;
}
__device__ __forceinline__ uint32_t rna_tf32(float x) {
    uint32_t r;
    asm("cvt.rna.tf32.f32 %0, %1;" : "=r"(r) : "f"(x));
    return r;
}
__device__ __forceinline__ void mma_tf32(float* c, const uint32_t* a, uint32_t b0, uint32_t b1) {
    asm volatile(
        "mma.sync.aligned.m16n8k8.row.col.f32.tf32.tf32.f32 "
        "{%0,%1,%2,%3}, {%4,%5,%6,%7}, {%8,%9}, {%0,%1,%2,%3};"
        : "+f"(c[0]), "+f"(c[1]), "+f"(c[2]), "+f"(c[3])
        : "r"(a[0]), "r"(a[1]), "r"(a[2]), "r"(a[3]), "r"(b0), "r"(b1));
}
__device__ __forceinline__ void ldsm_x4(uint32_t& r0, uint32_t& r1, uint32_t& r2, uint32_t& r3,
                                        uint32_t a) {
    asm volatile("ldmatrix.sync.aligned.m8n8.x4.shared.b16 {%0,%1,%2,%3}, [%4];"
                 : "=r"(r0), "=r"(r1), "=r"(r2), "=r"(r3) : "r"(a));
}
__device__ __forceinline__ void cp_async16(uint32_t dst, const void* src) {
    asm volatile("cp.async.cg.shared.global [%0], [%1], 16;" :: "r"(dst), "l"(src) : "memory");
}
__device__ __forceinline__ void cp_commit() { asm volatile("cp.async.commit_group;" ::: "memory"); }
__device__ __forceinline__ void cp_wait0()  { asm volatile("cp.async.wait_group 0;" ::: "memory"); }
__device__ __forceinline__ void cp_wait1()  { asm volatile("cp.async.wait_group 1;" ::: "memory"); }

// ---------------- Psi MLP layers 1-2 only: h2 (32) + ones column, transposed ----------------
__global__ void psi2_kernel(const float* __restrict__ xs, const float* __restrict__ vs,
                            const float* __restrict__ W1, const float* __restrict__ b1,
                            const float* __restrict__ W2, const float* __restrict__ b2)
{
    __shared__ float sW1[128];
    __shared__ float sb1[64];
    __shared__ float sW2[64 * 32];
    __shared__ float sb2[32];

    int tid = threadIdx.x;
    for (int i = tid; i < 128; i += 256)      sW1[i] = W1[i];
    for (int i = tid; i < 64; i += 256)       sb1[i] = b1[i];
    for (int i = tid; i < 64 * 32; i += 256)  sW2[i] = W2[i];
    if (tid < 32)                             sb2[tid] = b2[tid];
    __syncthreads();

    int p = blockIdx.x * 256 + tid;
    int v = p >> 9;
    int x = p & 511;
    float xin = xs[x];
    float vin = vs[v];

    float h1[64];
#pragma unroll
    for (int j = 0; j < 64; j++) {
        float s = fmaf(xin, sW1[j], fmaf(vin, sW1[64 + j], sb1[j]));
        h1[j] = fmaxf(s, 0.0f);
    }
#pragma unroll
    for (int j = 0; j < 32; j++) {
        float s = sb2[j];
#pragma unroll
        for (int i = 0; i < 64; i++) s = fmaf(h1[i], sW2[i * 32 + j], s);
        g_h2T[(size_t)j * NVX + p] = __uint_as_float(rna_tf32(fmaxf(s, 0.0f)));
    }
    g_h2T[(size_t)32 * NVX + p] = 1.0f;
#pragma unroll
    for (int j = 33; j < NH; j++)
        g_h2T[(size_t)j * NVX + p] = 0.0f;
}

// ---------------- phi table transposed + zero g_w2 (fused) ----------------
__global__ void phi_kernel(const float* __restrict__ x_out, const float* __restrict__ xs)
{
    int idx = blockIdx.x * 256 + threadIdx.x;
    if (idx < NT * NH) g_w2[idx] = 0.0f;
    if (idx >= NXOUT * KP) return;
    int n = idx / KP;
    int k = idx - n * KP;
    float val = 0.0f;
    if (k < KDIM) {
        float w = (2.0f * 3.14159265358979323846f) / (xs[NXS - 1] - xs[0]);
        float xo = x_out[n];
        if (k < 128) val = sinf((float)(k + 1) * w * xo);
        else         val = cosf((float)(k - 128) * w * xo);
        val = __uint_as_float(rna_tf32(val));
    }
    g_phiT[idx] = val;
}

// ---------------- GEMM1b: g_w2 (1024x48) += f (1024x65536) @ h2T^T ----------------
// CTA tile 128x48, BK=64, 192 threads: warps 2(M) x 3(N), warp tile 64x16.
// Split-K 36 (16 x 29 iters + 20 x 28 iters of BK=64), grid (1, 8, 36) = 288 CTAs, 2/SM.
#define B1_BM 128
#define B1_BN 48
#define B1_BK 64
#define B1_THREADS 192
#define B1_SPLITS 36
#define B1_SA 68                 // bank pattern (4r+j)%32 -> conflict-free ldmatrix
#define B1_A_FLOATS (B1_BM * B1_SA)     // 8704
#define B1_B_FLOATS (B1_BN * B1_SA)     // 3264
#define B1_STAGE (B1_A_FLOATS + B1_B_FLOATS)   // 11968
#define B1_SMEM_FLOATS (2 * B1_STAGE)          // 23936 floats = 95744 B

__global__ void __launch_bounds__(B1_THREADS, 2) gemm1b(const float* __restrict__ f)
{
    extern __shared__ __align__(16) float sm[];
    uint32_t sm_b = smem_u32(sm);

    const int tid = threadIdx.x;
    const int lane = tid & 31;
    const int warp = tid >> 5;               // 0..5
    const int wm = warp & 1;                 // 0..1 (M)
    const int wn = warp >> 1;                // 0..2 (N)
    const int q = lane >> 2, j = lane & 3;

    const int row0 = blockIdx.y * B1_BM;
    const int z = blockIdx.z;
    int it0, nit;
    if (z < 16) { it0 = z * 29;               nit = 29; }
    else        { it0 = 16 * 29 + (z - 16) * 28; nit = 28; }
    const size_t kb0 = (size_t)it0 * B1_BK;

    float acc[4][2][4];
#pragma unroll
    for (int a = 0; a < 4; a++)
#pragma unroll
        for (int b = 0; b < 2; b++)
#pragma unroll
            for (int c = 0; c < 4; c++) acc[a][b][c] = 0.0f;

    uint32_t a_u32[2], b_u32[2];
#pragma unroll
    for (int s = 0; s < 2; s++) {
        a_u32[s] = sm_b + (uint32_t)(s * B1_STAGE) * 4u;
        b_u32[s] = a_u32[s] + (uint32_t)B1_A_FLOATS * 4u;
    }

    const int arow = (lane & 7) + ((lane >> 3) & 1) * 8;
    const int acol = (lane >> 4) * 4;
    uint32_t offA[4];
#pragma unroll
    for (int mt = 0; mt < 4; mt++)
        offA[mt] = (uint32_t)(((wm * 64 + mt * 16 + arow) * B1_SA + acol) * 4);

    const int brow = (lane & 7);
    const int bsel = (lane >> 4);
    const int bcol = ((lane >> 3) & 1) * 4;
    const uint32_t offB = (uint32_t)(((wn * 16 + bsel * 8 + brow) * B1_SA + bcol) * 4);

    auto load_stage = [&](int s, size_t kb) {
        for (int idx = tid; idx < B1_BM * 16; idx += B1_THREADS) {
            int r = idx >> 4, o = idx & 15;
            cp_async16(a_u32[s] + (uint32_t)(r * B1_SA + o * 4) * 4,
                       f + (size_t)(row0 + r) * NVX + kb + o * 4);
        }
#pragma unroll
        for (int p = 0; p < 4; p++) {
            int idx = tid + p * B1_THREADS;
            int r = idx >> 4, o = idx & 15;
            cp_async16(b_u32[s] + (uint32_t)(r * B1_SA + o * 4) * 4,
                       g_h2T + (size_t)r * NVX + kb + o * 4);
        }
        cp_commit();
    };

    load_stage(0, kb0);
    load_stage(1, kb0 + B1_BK);

    for (int it = 0; it < nit; ++it) {
        const int s = it & 1;
        if (it + 1 < nit) cp_wait1(); else cp_wait0();
        __syncthreads();

        const uint32_t aS = a_u32[s];
        const uint32_t bS = b_u32[s];
#pragma unroll
        for (int kk = 0; kk < 8; kk++) {
            uint32_t afr[4][4];
#pragma unroll
            for (int mt = 0; mt < 4; mt++)
                ldsm_x4(afr[mt][0], afr[mt][1], afr[mt][2], afr[mt][3],
                        aS + offA[mt] + kk * 32);
            uint32_t bfr[2][2];
            ldsm_x4(bfr[0][0], bfr[0][1], bfr[1][0], bfr[1][1], bS + offB + kk * 32);
#pragma unroll
            for (int nt = 0; nt < 2; nt++)
#pragma unroll
                for (int mt = 0; mt < 4; mt++)
                    mma_tf32(acc[mt][nt], afr[mt], bfr[nt][0], bfr[nt][1]);
        }
        __syncthreads();
        if (it + 2 < nit)
            load_stage(s, kb0 + (size_t)(it + 2) * B1_BK);
    }

    // atomic accumulate into g_w2
#pragma unroll
    for (int mt = 0; mt < 4; mt++) {
        int r0 = row0 + wm * 64 + mt * 16 + q;
#pragma unroll
        for (int nt = 0; nt < 2; nt++) {
            int c0 = wn * 16 + nt * 8 + 2 * j;
            atomicAdd(&g_w2[r0 * NH + c0],           acc[mt][nt][0]);
            atomicAdd(&g_w2[r0 * NH + c0 + 1],       acc[mt][nt][1]);
            atomicAdd(&g_w2[(r0 + 8) * NH + c0],     acc[mt][nt][2]);
            atomicAdd(&g_w2[(r0 + 8) * NH + c0 + 1], acc[mt][nt][3]);
        }
    }
}

// ---------------- small gemm: g_w = rna(scale * g_w2 @ [W3; b3]), pad zeros ----------------
__global__ void small_gemm(const float* __restrict__ xs, const float* __restrict__ vs,
                           const float* __restrict__ W3, const float* __restrict__ b3)
{
    __shared__ float sa[33];
    int t = blockIdx.x;
    int tid = threadIdx.x;
    if (tid < 33) sa[tid] = g_w2[t * NH + tid];
    __syncthreads();
    float scale = (xs[1] - xs[0]) * (vs[1] - vs[0]);   // hx * hv
    for (int k = tid; k < KP; k += 256) {
        float s = 0.0f;
        if (k < KDIM) {
            s = sa[32] * b3[k];
#pragma unroll
            for (int jj = 0; jj < 32; jj++) s = fmaf(sa[jj], W3[jj * KDIM + k], s);
            s = __uint_as_float(rna_tf32(s * scale));
        }
        g_w[(size_t)t * KP + k] = s;
    }
}

// ---------------- GEMM2: out = g_w (1024x288) @ phiT^T (288x2048) ----------------
// CTA tile 64(M) x 128(N), BK=32, both operands streamed, 3-stage cp.async.
// 256 threads: warps 2(M) x 4(N), warp tile 32x32. Grid 16 x 16 = 256 CTAs, 2/SM.
#define BK 32
#define G2M 64
#define G2N 128
#define G2_ST 36
#define G2_A_STAGE (G2M * G2_ST)                   // 2304
#define G2_B_STAGE (G2N * G2_ST)                   // 4608
#define G2_STAGE (G2_A_STAGE + G2_B_STAGE)         // 6912
#define G2_SMEM_FLOATS (3 * G2_STAGE)              // 20736 floats = 82944 B

__global__ void __launch_bounds__(256, 2) gemm2_mma(float* __restrict__ out)
{
    extern __shared__ __align__(16) float sm[];
    uint32_t sm_b = smem_u32(sm);

    const int tid = threadIdx.x;
    const int lane = tid & 31;
    const int warp = tid >> 5;               // 0..7
    const int wm = warp & 1;                 // 0..1 (M)
    const int wn = warp >> 1;                // 0..3 (N)
    const int q = lane >> 2, j = lane & 3;

    const int row0 = blockIdx.y * G2M;
    const int col0 = blockIdx.x * G2N;

    uint32_t a_u32[3], b_u32[3];
#pragma unroll
    for (int s = 0; s < 3; s++) {
        a_u32[s] = sm_b + (uint32_t)(s * G2_STAGE) * 4u;
        b_u32[s] = a_u32[s] + (uint32_t)G2_A_STAGE * 4u;
    }

    auto load_stage = [&](int s, int k0) {
        // A: 64 rows x 8 float4 = 512 = 2/thread
#pragma unroll
        for (int p = 0; p < 2; p++) {
            int idx = tid + p * 256;
            int r = idx >> 3, o = idx & 7;
            cp_async16(a_u32[s] + (uint32_t)(r * G2_ST + o * 4) * 4,
                       g_w + (size_t)(row0 + r) * KP + k0 + o * 4);
        }
        // B: 128 rows x 8 float4 = 1024 = 4/thread
#pragma unroll
        for (int p = 0; p < 4; p++) {
            int idx = tid + p * 256;
            int r = idx >> 3, o = idx & 7;
            cp_async16(b_u32[s] + (uint32_t)(r * G2_ST + o * 4) * 4,
                       g_phiT + (size_t)(col0 + r) * KP + k0 + o * 4);
        }
        cp_commit();
    };
    load_stage(0, 0);
    load_stage(1, BK);

    // ldmatrix offsets
    const int arow = (lane & 7) + ((lane >> 3) & 1) * 8;
    const int acol = (lane >> 4) * 4;
    uint32_t offA[2];
#pragma unroll
    for (int mt = 0; mt < 2; mt++)
        offA[mt] = (uint32_t)(((wm * 32 + mt * 16 + arow) * G2_ST + acol) * 4);

    const int brow = (lane & 7);
    const int bsel = (lane >> 4);
    const int bcol = ((lane >> 3) & 1) * 4;
    uint32_t offB[2];
#pragma unroll
    for (int p = 0; p < 2; p++)
        offB[p] = (uint32_t)(((wn * 32 + (2 * p + bsel) * 8 + brow) * G2_ST + bcol) * 4);

    float acc[2][4][4];
#pragma unroll
    for (int a = 0; a < 2; a++)
#pragma unroll
        for (int b = 0; b < 4; b++)
#pragma unroll
            for (int c = 0; c < 4; c++) acc[a][b][c] = 0.0f;

    const int NIT2 = KP / BK;   // 9
    for (int it = 0; it < NIT2; ++it) {
        const int s = it % 3;
        if (it + 1 < NIT2) cp_wait1(); else cp_wait0();
        __syncthreads();

        if (it + 2 < NIT2) load_stage((s + 2) % 3, (it + 2) * BK);

        const uint32_t aS = a_u32[s];
        const uint32_t bS = b_u32[s];
#pragma unroll
        for (int kk = 0; kk < 4; kk++) {
            uint32_t afr[2][4];
#pragma unroll
            for (int mt = 0; mt < 2; mt++)
                ldsm_x4(afr[mt][0], afr[mt][1], afr[mt][2], afr[mt][3],
                        aS + offA[mt] + kk * 32);
            uint32_t bfr[4][2];
#pragma unroll
            for (int p = 0; p < 2; p++)
                ldsm_x4(bfr[2 * p][0], bfr[2 * p][1], bfr[2 * p + 1][0], bfr[2 * p + 1][1],
                        bS + offB[p] + kk * 32);
#pragma unroll
            for (int nt = 0; nt < 4; nt++)
#pragma unroll
                for (int mt = 0; mt < 2; mt++)
                    mma_tf32(acc[mt][nt], afr[mt], bfr[nt][0], bfr[nt][1]);
        }
    }

#pragma unroll
    for (int mt = 0; mt < 2; mt++) {
        int r0 = row0 + wm * 32 + mt * 16 + q;
#pragma unroll
        for (int nt = 0; nt < 4; nt++) {
            int c0 = col0 + wn * 32 + nt * 8 + 2 * j;
            *(float2*)&out[(size_t)r0 * NXOUT + c0]       = make_float2(acc[mt][nt][0], acc[mt][nt][1]);
            *(float2*)&out[(size_t)(r0 + 8) * NXOUT + c0] = make_float2(acc[mt][nt][2], acc[mt][nt][3]);
        }
    }
}

extern "C" void kernel_launch(void* const* d_in, const int* in_sizes, int n_in,
                              void* d_out, int out_size)
{
    const float* x_out = (const float*)d_in[0];
    const float* f     = (const float*)d_in[1];
    const float* xs    = (const float*)d_in[2];
    const float* vs    = (const float*)d_in[3];
    const float* W1    = (const float*)d_in[4];
    const float* b1    = (const float*)d_in[5];
    const float* W2    = (const float*)d_in[6];
    const float* b2    = (const float*)d_in[7];
    const float* W3    = (const float*)d_in[8];
    const float* b3    = (const float*)d_in[9];
    float* out = (float*)d_out;

    static int smem_set = 0;
    if (!smem_set) {
        cudaFuncSetAttribute(gemm1b, cudaFuncAttributeMaxDynamicSharedMemorySize,
                             B1_SMEM_FLOATS * 4);
        cudaFuncSetAttribute(gemm2_mma, cudaFuncAttributeMaxDynamicSharedMemorySize,
                             G2_SMEM_FLOATS * 4);
        smem_set = 1;
    }

    psi2_kernel<<<NVX / 256, 256>>>(xs, vs, W1, b1, W2, b2);
    phi_kernel<<<(NXOUT * KP + 255) / 256, 256>>>(x_out, xs);
    {
        dim3 grid(1, NT / B1_BM, B1_SPLITS);   // 1 x 8 x 36 = 288 CTAs
        gemm1b<<<grid, B1_THREADS, B1_SMEM_FLOATS * 4>>>(f);
    }
    small_gemm<<<NT, 256>>>(xs, vs, W3, b3);
    {
        dim3 grid(NXOUT / G2N, NT / G2M);      // 16 x 16 = 256 CTAs
        gemm2_mma<<<grid, 256, G2_SMEM_FLOATS * 4>>>(out);
    }
}